// round 6
// baseline (speedup 1.0000x reference)
#include <cuda_runtime.h>
#include <cuda_bf16.h>
#include <cstdint>

#define N_NODES 50000
#define N_EDGES 600000
#define HID     128
#define N_GRAPHS 512
#define BN_EPS  1e-5f

// ---------------- scratch (static device allocations) ----------------
__device__ float g_h1[N_NODES * HID];   // GIN output (f32)
__device__ float g_hs[N_NODES * HID];   // SAGE0 output (f32)
__device__ float g_t2[N_NODES * HID];   // SAGE1 output (f32)

__device__ __nv_bfloat16 g_p1hi[N_NODES * HID], g_p1lo[N_NODES * HID]; // GIN agg out
__device__ __nv_bfloat16 g_nhi[N_NODES * HID],  g_nlo[N_NODES * HID];  // neigh
__device__ __nv_bfloat16 g_bhi[N_NODES * HID],  g_blo[N_NODES * HID];  // hbn (self)
__device__ __nv_bfloat16 g_whi[6 * HID * HID],  g_wlo[6 * HID * HID];  // weights

__device__ int   g_deg[N_NODES];
__device__ int   g_off[N_NODES + 1];
__device__ int   g_cur[N_NODES];
__device__ int   g_csr[N_EDGES];
__device__ float g_invdeg[N_NODES];

__device__ float g_bnsum[HID];
__device__ float g_bnsq[HID];
__device__ float g_scale[HID];
__device__ float g_shift[HID];

// ---------------- helpers ----------------
__device__ __forceinline__ uint32_t smem_u32(const void* p) {
    uint32_t a;
    asm("{ .reg .u64 t; cvta.to.shared.u64 t, %1; cvt.u32.u64 %0, t; }" : "=r"(a) : "l"(p));
    return a;
}

#define CP_ASYNC16(dst, src) \
    asm volatile("cp.async.cg.shared.global [%0], [%1], 16;" :: "r"(dst), "l"(src))
#define CP_COMMIT() asm volatile("cp.async.commit_group;" ::: "memory")
#define CP_WAIT0()  asm volatile("cp.async.wait_group 0;" ::: "memory")

#define LDSM_X4(r, addr) \
    asm volatile("ldmatrix.sync.aligned.m8n8.x4.shared.b16 {%0,%1,%2,%3},[%4];" \
        : "=r"((r)[0]), "=r"((r)[1]), "=r"((r)[2]), "=r"((r)[3]) : "r"(addr))
#define LDSM_X4T(r, addr) \
    asm volatile("ldmatrix.sync.aligned.m8n8.x4.trans.shared.b16 {%0,%1,%2,%3},[%4];" \
        : "=r"((r)[0]), "=r"((r)[1]), "=r"((r)[2]), "=r"((r)[3]) : "r"(addr))

#define MMA_BF16(c, a, b0, b1) \
    asm volatile("mma.sync.aligned.m16n8k16.row.col.f32.bf16.bf16.f32 " \
        "{%0,%1,%2,%3},{%4,%5,%6,%7},{%8,%9},{%0,%1,%2,%3};" \
        : "+f"((c)[0]), "+f"((c)[1]), "+f"((c)[2]), "+f"((c)[3]) \
        : "r"((a)[0]), "r"((a)[1]), "r"((a)[2]), "r"((a)[3]), "r"(b0), "r"(b1))

__device__ __forceinline__ uint32_t packbf(float x, float y) {
    __nv_bfloat162 t = __floats2bfloat162_rn(x, y);
    return *(uint32_t*)&t;
}

__device__ __forceinline__ void split2(float x, float y, uint32_t& h, uint32_t& l) {
    __nv_bfloat16 hx = __float2bfloat16(x), hy = __float2bfloat16(y);
    h = packbf(x, y);  // rn-packed hi
    // recompute hi exactly as packed for residual
    __nv_bfloat162 hh = *(__nv_bfloat162*)&h;
    l = packbf(x - __bfloat162float(hh.x), y - __bfloat162float(hh.y));
    (void)hx; (void)hy;
}

// smem layout (bytes), A-plane stride 56 bf16 (112B: 16B-mult, bank-shift 28),
// B/T-plane stride 136 bf16 (272B: 16B-mult, bank-shift 4)
#define A_STRIDE 56
#define B_STRIDE 136
#define A_PL_BYTES (128 * A_STRIDE * 2)     // 14336
#define B_PL_BYTES (32 * B_STRIDE * 2)      // 8704
#define T_PL_BYTES (128 * B_STRIDE * 2)     // 34816
#define OFF_ALO  A_PL_BYTES
#define OFF_BHI  (2 * A_PL_BYTES)
#define OFF_BLO  (2 * A_PL_BYTES + B_PL_BYTES)
#define SAGE_SMEM (2 * A_PL_BYTES + 2 * B_PL_BYTES)             // 46080
#define OFF_THI  SAGE_SMEM
#define OFF_TLO  (SAGE_SMEM + T_PL_BYTES)
#define GIN_SMEM (SAGE_SMEM + 2 * T_PL_BYTES)                   // 115712

// ---------------- setup kernels ----------------
__global__ void zero_init_kernel() {
    int i = blockIdx.x * blockDim.x + threadIdx.x;
    if (i < N_NODES) g_deg[i] = 0;
    if (i < HID) { g_bnsum[i] = 0.f; g_bnsq[i] = 0.f; }
}

__global__ void hist_kernel(const int* __restrict__ dst) {
    int e = blockIdx.x * blockDim.x + threadIdx.x;
    if (e < N_EDGES) atomicAdd(&g_deg[dst[e]], 1);
}

__global__ void scan_kernel() {
    __shared__ int sh[1024];
    const int CH = (N_NODES + 1023) / 1024;  // 49
    int t = threadIdx.x;
    int base = t * CH;
    int tsum = 0;
    for (int i = 0; i < CH; i++) {
        int idx = base + i;
        if (idx < N_NODES) tsum += g_deg[idx];
    }
    sh[t] = tsum;
    __syncthreads();
    for (int off = 1; off < 1024; off <<= 1) {
        int v = (t >= off) ? sh[t - off] : 0;
        __syncthreads();
        sh[t] += v;
        __syncthreads();
    }
    int run = sh[t] - tsum;
    for (int i = 0; i < CH; i++) {
        int idx = base + i;
        if (idx < N_NODES) {
            int d = g_deg[idx];
            g_off[idx] = run;
            g_cur[idx] = run;
            g_invdeg[idx] = 1.0f / (float)max(d, 1);
            run += d;
        }
    }
    if (t == 1023) g_off[N_NODES] = sh[1023];
}

__global__ void scatter_kernel(const int* __restrict__ src, const int* __restrict__ dst) {
    int e = blockIdx.x * blockDim.x + threadIdx.x;
    if (e < N_EDGES) {
        int d = dst[e];
        int p = atomicAdd(&g_cur[d], 1);
        g_csr[p] = src[e];
    }
}

// weight f32 -> bf16 hi/lo planes (6 matrices)
__global__ void wconv_kernel(const float* __restrict__ w0, const float* __restrict__ w1,
                             const float* __restrict__ w2, const float* __restrict__ w3,
                             const float* __restrict__ w4, const float* __restrict__ w5) {
    int i = blockIdx.x * blockDim.x + threadIdx.x;
    if (i >= 6 * HID * HID) return;
    int m = i >> 14, off = i & 16383;
    const float* s = (m == 0) ? w0 : (m == 1) ? w1 : (m == 2) ? w2
                   : (m == 3) ? w3 : (m == 4) ? w4 : w5;
    float v = s[off];
    __nv_bfloat16 h = __float2bfloat16(v);
    g_whi[i] = h;
    g_wlo[i] = __float2bfloat16(v - __bfloat162float(h));
}

// ---------------- aggregation kernels (warp per node, write bf16 planes) ----------------
__global__ void gin_agg_kernel(const float* __restrict__ x) {
    int w = (blockIdx.x * blockDim.x + threadIdx.x) >> 5;
    int lane = threadIdx.x & 31;
    if (w >= N_NODES) return;
    const float4* x4 = (const float4*)x;
    float4 acc = __ldg(&x4[w * 32 + lane]);
    int e = g_off[w], end = g_off[w + 1];
    for (; e + 4 <= end; e += 4) {
        int s0 = g_csr[e + 0], s1 = g_csr[e + 1], s2 = g_csr[e + 2], s3 = g_csr[e + 3];
        float4 v0 = __ldg(&x4[s0 * 32 + lane]);
        float4 v1 = __ldg(&x4[s1 * 32 + lane]);
        float4 v2 = __ldg(&x4[s2 * 32 + lane]);
        float4 v3 = __ldg(&x4[s3 * 32 + lane]);
        acc.x += v0.x + v1.x + v2.x + v3.x;
        acc.y += v0.y + v1.y + v2.y + v3.y;
        acc.z += v0.z + v1.z + v2.z + v3.z;
        acc.w += v0.w + v1.w + v2.w + v3.w;
    }
    for (; e < end; e++) {
        int s0 = g_csr[e];
        float4 v0 = __ldg(&x4[s0 * 32 + lane]);
        acc.x += v0.x; acc.y += v0.y; acc.z += v0.z; acc.w += v0.w;
    }
    uint32_t h0, l0, h1, l1;
    split2(acc.x, acc.y, h0, l0);
    split2(acc.z, acc.w, h1, l1);
    ((uint2*)g_p1hi)[w * 32 + lane] = make_uint2(h0, h1);
    ((uint2*)g_p1lo)[w * 32 + lane] = make_uint2(l0, l1);
}

__device__ __forceinline__ float4 bn_relu4(float4 h, float4 sc, float4 sh) {
    float4 r;
    r.x = fmaxf(fmaf(h.x, sc.x, sh.x), 0.f);
    r.y = fmaxf(fmaf(h.y, sc.y, sh.y), 0.f);
    r.z = fmaxf(fmaf(h.z, sc.z, sh.z), 0.f);
    r.w = fmaxf(fmaf(h.w, sc.w, sh.w), 0.f);
    return r;
}

__global__ void sage_agg_kernel(const float* __restrict__ hraw) {
    int w = (blockIdx.x * blockDim.x + threadIdx.x) >> 5;
    int lane = threadIdx.x & 31;
    if (w >= N_NODES) return;
    float4 sc = *(const float4*)&g_scale[lane * 4];
    float4 sh = *(const float4*)&g_shift[lane * 4];
    const float4* h4 = (const float4*)hraw;

    float4 self = bn_relu4(__ldg(&h4[w * 32 + lane]), sc, sh);
    {
        uint32_t h0, l0, h1, l1;
        split2(self.x, self.y, h0, l0);
        split2(self.z, self.w, h1, l1);
        ((uint2*)g_bhi)[w * 32 + lane] = make_uint2(h0, h1);
        ((uint2*)g_blo)[w * 32 + lane] = make_uint2(l0, l1);
    }

    float4 acc = make_float4(0.f, 0.f, 0.f, 0.f);
    int e = g_off[w], end = g_off[w + 1];
    for (; e + 4 <= end; e += 4) {
        int s0 = g_csr[e + 0], s1 = g_csr[e + 1], s2 = g_csr[e + 2], s3 = g_csr[e + 3];
        float4 v0 = bn_relu4(__ldg(&h4[s0 * 32 + lane]), sc, sh);
        float4 v1 = bn_relu4(__ldg(&h4[s1 * 32 + lane]), sc, sh);
        float4 v2 = bn_relu4(__ldg(&h4[s2 * 32 + lane]), sc, sh);
        float4 v3 = bn_relu4(__ldg(&h4[s3 * 32 + lane]), sc, sh);
        acc.x += v0.x + v1.x + v2.x + v3.x;
        acc.y += v0.y + v1.y + v2.y + v3.y;
        acc.z += v0.z + v1.z + v2.z + v3.z;
        acc.w += v0.w + v1.w + v2.w + v3.w;
    }
    for (; e < end; e++) {
        int s0 = g_csr[e];
        float4 v0 = bn_relu4(__ldg(&h4[s0 * 32 + lane]), sc, sh);
        acc.x += v0.x; acc.y += v0.y; acc.z += v0.z; acc.w += v0.w;
    }
    float id = g_invdeg[w];
    acc.x *= id; acc.y *= id; acc.z *= id; acc.w *= id;
    {
        uint32_t h0, l0, h1, l1;
        split2(acc.x, acc.y, h0, l0);
        split2(acc.z, acc.w, h1, l1);
        ((uint2*)g_nhi)[w * 32 + lane] = make_uint2(h0, h1);
        ((uint2*)g_nlo)[w * 32 + lane] = make_uint2(l0, l1);
    }
}

// ---------------- GEMM building blocks (bf16 split mma) ----------------
// stage A chunk [128 rows x 32 k] bf16 planes via cp.async
__device__ __forceinline__ void cpA(uint32_t uAhi, uint32_t uAlo,
                                    const __nv_bfloat16* __restrict__ gHi,
                                    const __nv_bfloat16* __restrict__ gLo,
                                    int rowBase, int kc, int M, int tid) {
#pragma unroll
    for (int i = 0; i < 2; i++) {
        int f = tid + 256 * i;       // 0..511
        int r = f >> 2, j = f & 3;
        int gr = rowBase + r; if (gr >= M) gr = M - 1;
        uint32_t d = (uint32_t)(r * A_STRIDE + j * 8) * 2u;
        const __nv_bfloat16* s = gHi + gr * HID + kc + j * 8;
        CP_ASYNC16(uAhi + d, s);
        CP_ASYNC16(uAlo + d, gLo + gr * HID + kc + j * 8);
    }
}

// stage B chunk [32 k x 128 n] bf16 planes
__device__ __forceinline__ void cpB(uint32_t uBhi, uint32_t uBlo,
                                    const __nv_bfloat16* __restrict__ wHi,
                                    const __nv_bfloat16* __restrict__ wLo,
                                    int kc, int tid) {
#pragma unroll
    for (int i = 0; i < 2; i++) {
        int f = tid + 256 * i;       // 0..511
        int k = f >> 4, nj = f & 15;
        uint32_t d = (uint32_t)(k * B_STRIDE + nj * 8) * 2u;
        CP_ASYNC16(uBhi + d, wHi + (kc + k) * HID + nj * 8);
        CP_ASYNC16(uBlo + d, wLo + (kc + k) * HID + nj * 8);
    }
}

// one 32-k chunk of MMAs; A planes at uAhi/uAlo with stride astride (bf16 units)
__device__ __forceinline__ void mma_chunk(uint32_t uAhi, uint32_t uAlo, int astride,
                                          uint32_t uBhi, uint32_t uBlo,
                                          int warpM, int warpN, int lane,
                                          float c[2][8][4]) {
    int sub = lane >> 3, l7 = lane & 7;
    int a_roff = (sub & 1) * 8 + l7;
    int a_koff = (sub >> 1) * 8;
    int b_koff = (sub & 1) * 8 + l7;
    int b_noff = (sub >> 1) * 8;
#pragma unroll
    for (int k0 = 0; k0 < 32; k0 += 16) {
        uint32_t ah[2][4], al[2][4];
#pragma unroll
        for (int mt = 0; mt < 2; mt++) {
            int r = warpM * 32 + mt * 16 + a_roff;
            uint32_t ao = (uint32_t)(r * astride + k0 + a_koff) * 2u;
            LDSM_X4(ah[mt], uAhi + ao);
            LDSM_X4(al[mt], uAlo + ao);
        }
#pragma unroll
        for (int np = 0; np < 4; np++) {
            int n0 = warpN * 64 + np * 16;
            uint32_t bo = (uint32_t)((k0 + b_koff) * B_STRIDE + n0 + b_noff) * 2u;
            uint32_t bh[4], bl[4];
            LDSM_X4T(bh, uBhi + bo);
            LDSM_X4T(bl, uBlo + bo);
#pragma unroll
            for (int mt = 0; mt < 2; mt++) {
                MMA_BF16(c[mt][2 * np],     ah[mt], bh[0], bh[1]);
                MMA_BF16(c[mt][2 * np + 1], ah[mt], bh[2], bh[3]);
                MMA_BF16(c[mt][2 * np],     al[mt], bh[0], bh[1]);
                MMA_BF16(c[mt][2 * np + 1], al[mt], bh[2], bh[3]);
                MMA_BF16(c[mt][2 * np],     ah[mt], bl[0], bl[1]);
                MMA_BF16(c[mt][2 * np + 1], ah[mt], bl[2], bl[3]);
            }
        }
    }
}

// epilogue: bias + store f32 + BN stats (mma acc layout)
__device__ __forceinline__ void mma_epilogue(float c[2][8][4],
                                             const float* __restrict__ bias,
                                             float* __restrict__ out,
                                             float* csum, float* csq,
                                             int rowBase, int warpM, int warpN,
                                             int lane, int M, int tid) {
    int g = lane >> 2, t4 = lane & 3;
#pragma unroll
    for (int nt = 0; nt < 8; nt++) {
        int n0 = warpN * 64 + nt * 8 + 2 * t4;
        float b0v = __ldg(&bias[n0]);
        float b1v = __ldg(&bias[n0 + 1]);
        float lsum0 = 0.f, lsum1 = 0.f, lsq0 = 0.f, lsq1 = 0.f;
#pragma unroll
        for (int mt = 0; mt < 2; mt++) {
            int row0 = rowBase + warpM * 32 + mt * 16 + g;
            float v00 = c[mt][nt][0] + b0v, v01 = c[mt][nt][1] + b1v;
            float v10 = c[mt][nt][2] + b0v, v11 = c[mt][nt][3] + b1v;
            if (row0 < M) {
                *(float2*)&out[row0 * HID + n0] = make_float2(v00, v01);
                lsum0 += v00; lsum1 += v01; lsq0 += v00 * v00; lsq1 += v01 * v01;
            }
            if (row0 + 8 < M) {
                *(float2*)&out[(row0 + 8) * HID + n0] = make_float2(v10, v11);
                lsum0 += v10; lsum1 += v11; lsq0 += v10 * v10; lsq1 += v11 * v11;
            }
        }
        atomicAdd(&csum[n0], lsum0);
        atomicAdd(&csum[n0 + 1], lsum1);
        atomicAdd(&csq[n0], lsq0);
        atomicAdd(&csq[n0 + 1], lsq1);
    }
    __syncthreads();
    if (tid < HID) {
        atomicAdd(&g_bnsum[tid], csum[tid]);
        atomicAdd(&g_bnsq[tid], csq[tid]);
    }
}

// ---------------- SAGE GEMM: out = A1@W1 + A2@W2 + bias (+stats) ----------------
__global__ __launch_bounds__(256, 2) void sage_mma_kernel(
    const __nv_bfloat16* __restrict__ a1Hi, const __nv_bfloat16* __restrict__ a1Lo,
    const __nv_bfloat16* __restrict__ w1Hi, const __nv_bfloat16* __restrict__ w1Lo,
    const __nv_bfloat16* __restrict__ a2Hi, const __nv_bfloat16* __restrict__ a2Lo,
    const __nv_bfloat16* __restrict__ w2Hi, const __nv_bfloat16* __restrict__ w2Lo,
    const float* __restrict__ bias, float* __restrict__ out, int M)
{
    extern __shared__ char smem[];
    uint32_t sb = smem_u32(smem);
    uint32_t uAhi = sb, uAlo = sb + OFF_ALO, uBhi = sb + OFF_BHI, uBlo = sb + OFF_BLO;
    __shared__ float csum[HID], csq[HID];

    int tid = threadIdx.x, lane = tid & 31, warp = tid >> 5;
    int warpM = warp & 3, warpN = warp >> 2;
    int rowBase = blockIdx.x * 128;

    float c[2][8][4];
#pragma unroll
    for (int mt = 0; mt < 2; mt++)
#pragma unroll
        for (int nt = 0; nt < 8; nt++)
#pragma unroll
            for (int i = 0; i < 4; i++) c[mt][nt][i] = 0.f;
    if (tid < HID) { csum[tid] = 0.f; csq[tid] = 0.f; }

    const __nv_bfloat16* aH[2] = { a1Hi, a2Hi };
    const __nv_bfloat16* aL[2] = { a1Lo, a2Lo };
    const __nv_bfloat16* wH[2] = { w1Hi, w2Hi };
    const __nv_bfloat16* wL[2] = { w1Lo, w2Lo };

    for (int part = 0; part < 2; part++) {
        for (int cc = 0; cc < 4; cc++) {
            int kc = cc * 32;
            __syncthreads();
            cpA(uAhi, uAlo, aH[part], aL[part], rowBase, kc, M, tid);
            cpB(uBhi, uBlo, wH[part], wL[part], kc, tid);
            CP_COMMIT();
            CP_WAIT0();
            __syncthreads();
            mma_chunk(uAhi, uAlo, A_STRIDE, uBhi, uBlo, warpM, warpN, lane, c);
        }
    }
    mma_epilogue(c, bias, out, csum, csq, rowBase, warpM, warpN, lane, M, tid);
}

// ---------------- fused GIN MLP: out = relu(A@W1+b1)@W2 + b2 (+stats) ----------------
__global__ __launch_bounds__(256, 2) void gin_mma_kernel(
    const __nv_bfloat16* __restrict__ aHi, const __nv_bfloat16* __restrict__ aLo,
    const __nv_bfloat16* __restrict__ w1Hi, const __nv_bfloat16* __restrict__ w1Lo,
    const float* __restrict__ b1,
    const __nv_bfloat16* __restrict__ w2Hi, const __nv_bfloat16* __restrict__ w2Lo,
    const float* __restrict__ b2,
    float* __restrict__ out, int M)
{
    extern __shared__ char smem[];
    uint32_t sb = smem_u32(smem);
    uint32_t uAhi = sb, uAlo = sb + OFF_ALO, uBhi = sb + OFF_BHI, uBlo = sb + OFF_BLO;
    uint32_t uThi = sb + OFF_THI, uTlo = sb + OFF_TLO;
    __nv_bfloat16* Thi = (__nv_bfloat16*)(smem + OFF_THI);
    __nv_bfloat16* Tlo = (__nv_bfloat16*)(smem + OFF_TLO);
    __shared__ float csum[HID], csq[HID];

    int tid = threadIdx.x, lane = tid & 31, warp = tid >> 5;
    int warpM = warp & 3, warpN = warp >> 2;
    int g = lane >> 2, t4 = lane & 3;
    int rowBase = blockIdx.x * 128;

    float c[2][8][4];
#pragma unroll
    for (int mt = 0; mt < 2; mt++)
#pragma unroll
        for (int nt = 0; nt < 8; nt++)
#pragma unroll
            for (int i = 0; i < 4; i++) c[mt][nt][i] = 0.f;
    if (tid < HID) { csum[tid] = 0.f; csq[tid] = 0.f; }

    // phase 1: t = relu(A @ W1 + b1)
    for (int cc = 0; cc < 4; cc++) {
        int kc = cc * 32;
        __syncthreads();
        cpA(uAhi, uAlo, aHi, aLo, rowBase, kc, M, tid);
        cpB(uBhi, uBlo, w1Hi, w1Lo, kc, tid);
        CP_COMMIT();
        CP_WAIT0();
        __syncthreads();
        mma_chunk(uAhi, uAlo, A_STRIDE, uBhi, uBlo, warpM, warpN, lane, c);
    }

    // phase-1 epilogue: split t into T planes (transposed nothing: row-major [m][k])
    __syncthreads();
#pragma unroll
    for (int nt = 0; nt < 8; nt++) {
        int n0 = warpN * 64 + nt * 8 + 2 * t4;
        float b0v = __ldg(&b1[n0]);
        float b1v = __ldg(&b1[n0 + 1]);
#pragma unroll
        for (int mt = 0; mt < 2; mt++) {
            int r0 = warpM * 32 + mt * 16 + g;
            float v00 = fmaxf(c[mt][nt][0] + b0v, 0.f);
            float v01 = fmaxf(c[mt][nt][1] + b1v, 0.f);
            float v10 = fmaxf(c[mt][nt][2] + b0v, 0.f);
            float v11 = fmaxf(c[mt][nt][3] + b1v, 0.f);
            uint32_t h, l;
            split2(v00, v01, h, l);
            *(uint32_t*)(Thi + r0 * B_STRIDE + n0) = h;
            *(uint32_t*)(Tlo + r0 * B_STRIDE + n0) = l;
            split2(v10, v11, h, l);
            *(uint32_t*)(Thi + (r0 + 8) * B_STRIDE + n0) = h;
            *(uint32_t*)(Tlo + (r0 + 8) * B_STRIDE + n0) = l;
            c[mt][nt][0] = 0.f; c[mt][nt][1] = 0.f;
            c[mt][nt][2] = 0.f; c[mt][nt][3] = 0.f;
        }
    }

    // phase 2: out = t @ W2 + b2 (A from T planes, stride B_STRIDE)
    for (int cc = 0; cc < 4; cc++) {
        int kc = cc * 32;
        __syncthreads();
        cpB(uBhi, uBlo, w2Hi, w2Lo, kc, tid);
        CP_COMMIT();
        CP_WAIT0();
        __syncthreads();
        mma_chunk(uThi + (uint32_t)kc * 2u, uTlo + (uint32_t)kc * 2u, B_STRIDE,
                  uBhi, uBlo, warpM, warpN, lane, c);
    }
    mma_epilogue(c, b2, out, csum, csq, rowBase, warpM, warpN, lane, M, tid);
}

// ---------------- BN finalize ----------------
__global__ void bn_finalize_kernel(const float* __restrict__ gamma, const float* __restrict__ beta) {
    int c = threadIdx.x;
    const float invn = 1.0f / (float)N_NODES;
    float m = g_bnsum[c] * invn;
    float var = g_bnsq[c] * invn - m * m;
    var = fmaxf(var, 0.f);
    float s = gamma[c] * rsqrtf(var + BN_EPS);
    g_scale[c] = s;
    g_shift[c] = beta[c] - m * s;
    g_bnsum[c] = 0.f;
    g_bnsq[c] = 0.f;
}

// ---------------- pooling: batch is sorted, block per graph ----------------
__device__ __forceinline__ int lbound(const int* a, int n, int v) {
    int lo = 0, hi = n;
    while (lo < hi) {
        int mid = (lo + hi) >> 1;
        if (a[mid] < v) lo = mid + 1; else hi = mid;
    }
    return lo;
}

__global__ void pool_kernel(const float* __restrict__ hraw,
                            const int* __restrict__ batch,
                            float* __restrict__ out) {
    int gg = blockIdx.x;
    int c = threadIdx.x;
    int start = lbound(batch, N_NODES, gg);
    int end = lbound(batch, N_NODES, gg + 1);
    int cnt = end - start;
    float sc = g_scale[c], sh = g_shift[c];
    float s = 0.f;
    for (int i = start; i < end; i++) {
        float v = fmaf(hraw[i * HID + c], sc, sh);
        s += fmaxf(v, 0.f);
    }
    out[gg * HID + c] = s / fmaxf((float)cnt, 1.f);
}

// ---------------- launch ----------------
extern "C" void kernel_launch(void* const* d_in, const int* in_sizes, int n_in,
                              void* d_out, int out_size) {
    (void)in_sizes; (void)n_in; (void)out_size;
    const float* x       = (const float*)d_in[0];
    const int*   eidx    = (const int*)d_in[1];
    const int*   batch   = (const int*)d_in[2];
    const float* gin_w1  = (const float*)d_in[3];
    const float* gin_b1  = (const float*)d_in[4];
    const float* gin_w2  = (const float*)d_in[5];
    const float* gin_b2  = (const float*)d_in[6];
    const float* sage_wl = (const float*)d_in[7];
    const float* sage_bl = (const float*)d_in[8];
    const float* sage_wr = (const float*)d_in[9];
    const float* bn_g    = (const float*)d_in[10];
    const float* bn_b    = (const float*)d_in[11];
    float* out = (float*)d_out;

    const int* src = eidx;
    const int* dst = eidx + N_EDGES;

    float *p_h1, *p_hs, *p_t2;
    cudaGetSymbolAddress((void**)&p_h1, g_h1);
    cudaGetSymbolAddress((void**)&p_hs, g_hs);
    cudaGetSymbolAddress((void**)&p_t2, g_t2);
    __nv_bfloat16 *p_p1hi, *p_p1lo, *p_nhi, *p_nlo, *p_bhi, *p_blo, *p_whi, *p_wlo;
    cudaGetSymbolAddress((void**)&p_p1hi, g_p1hi);
    cudaGetSymbolAddress((void**)&p_p1lo, g_p1lo);
    cudaGetSymbolAddress((void**)&p_nhi, g_nhi);
    cudaGetSymbolAddress((void**)&p_nlo, g_nlo);
    cudaGetSymbolAddress((void**)&p_bhi, g_bhi);
    cudaGetSymbolAddress((void**)&p_blo, g_blo);
    cudaGetSymbolAddress((void**)&p_whi, g_whi);
    cudaGetSymbolAddress((void**)&p_wlo, g_wlo);

    const int M = N_NODES;
    const int gemmGrid = (M + 127) / 128;            // 391
    const int aggGrid = (N_NODES * 32 + 255) / 256;
    const int edgeGrid = (N_EDGES + 255) / 256;
    const int W = HID * HID;

    static int attr_set = 0;
    if (!attr_set) {
        cudaFuncSetAttribute(gin_mma_kernel, cudaFuncAttributeMaxDynamicSharedMemorySize, GIN_SMEM);
        cudaFuncSetAttribute(sage_mma_kernel, cudaFuncAttributeMaxDynamicSharedMemorySize, SAGE_SMEM);
        attr_set = 1;
    }

    // weight conversion + CSR build
    wconv_kernel<<<(6 * W + 255) / 256, 256>>>(gin_w1, gin_w2, sage_wl, sage_wr,
                                               sage_wl + W, sage_wr + W);
    zero_init_kernel<<<(N_NODES + 255) / 256, 256>>>();
    hist_kernel<<<edgeGrid, 256>>>(dst);
    scan_kernel<<<1, 1024>>>();
    scatter_kernel<<<edgeGrid, 256>>>(src, dst);

    // Layer 0: GIN (fused MLP)
    gin_agg_kernel<<<aggGrid, 256>>>(x);
    gin_mma_kernel<<<gemmGrid, 256, GIN_SMEM>>>(p_p1hi, p_p1lo,
                                                p_whi + 0 * W, p_wlo + 0 * W, gin_b1,
                                                p_whi + 1 * W, p_wlo + 1 * W, gin_b2,
                                                p_h1, M);
    bn_finalize_kernel<<<1, HID>>>(bn_g + 0 * HID, bn_b + 0 * HID);

    // SAGE layer 0
    sage_agg_kernel<<<aggGrid, 256>>>(p_h1);
    sage_mma_kernel<<<gemmGrid, 256, SAGE_SMEM>>>(p_nhi, p_nlo, p_whi + 2 * W, p_wlo + 2 * W,
                                                  p_bhi, p_blo, p_whi + 3 * W, p_wlo + 3 * W,
                                                  sage_bl, p_hs, M);
    bn_finalize_kernel<<<1, HID>>>(bn_g + 1 * HID, bn_b + 1 * HID);

    // SAGE layer 1
    sage_agg_kernel<<<aggGrid, 256>>>(p_hs);
    sage_mma_kernel<<<gemmGrid, 256, SAGE_SMEM>>>(p_nhi, p_nlo, p_whi + 4 * W, p_wlo + 4 * W,
                                                  p_bhi, p_blo, p_whi + 5 * W, p_wlo + 5 * W,
                                                  sage_bl + HID, p_t2, M);
    bn_finalize_kernel<<<1, HID>>>(bn_g + 2 * HID, bn_b + 2 * HID);

    // global mean pool (batch sorted)
    pool_kernel<<<N_GRAPHS, HID>>>(p_t2, batch, out);
}

// round 7
// speedup vs baseline: 1.3587x; 1.3587x over previous
#include <cuda_runtime.h>
#include <cuda_bf16.h>
#include <cstdint>

#define N_NODES 50000
#define N_EDGES 600000
#define HID     128
#define N_GRAPHS 512
#define BN_EPS  1e-5f
#define SCAN_BLOCKS ((N_NODES + 255) / 256)   // 196

// ---------------- scratch (static device allocations; no cudaMalloc) ----------------
__device__ float g_h0[N_NODES * HID];
__device__ float g_h1[N_NODES * HID];
__device__ float g_hbn[N_NODES * HID];
__device__ float g_neigh[N_NODES * HID];
__device__ float g_t2[N_NODES * HID];

__device__ int   g_deg[N_NODES];
__device__ int   g_off[N_NODES + 1];
__device__ int   g_cur[N_NODES];
__device__ int   g_csr[N_EDGES];
__device__ float g_invdeg[N_NODES];
__device__ int   g_blk[SCAN_BLOCKS];
__device__ int   g_blkoff[SCAN_BLOCKS];

__device__ float g_bnsum[HID];
__device__ float g_bnsq[HID];
__device__ float g_scale[HID];
__device__ float g_shift[HID];

// ---------------- helpers ----------------
__device__ __forceinline__ unsigned long long pack_dup(float x) {
    unsigned long long d;
    asm("mov.b64 %0,{%1,%1};" : "=l"(d) : "f"(x));
    return d;
}

// transposed A layout: element (k, row) at k*132 + 4*(k>>2) + row (conflict-free)
#define AS_IDX(k, row) ((k) * 132 + 4 * ((k) >> 2) + (row))
#define AS_SIZE 4256
// B layout: element (k, n) at k*132 + n
#define BS_IDX(k, n) ((k) * 132 + (n))
#define BS_SIZE 4224
#define TS_SIZE 17024

// ---------------- setup kernels ----------------
__global__ void zero_init_kernel() {
    int i = blockIdx.x * blockDim.x + threadIdx.x;
    if (i < N_NODES) g_deg[i] = 0;
    if (i < HID) { g_bnsum[i] = 0.f; g_bnsq[i] = 0.f; }
}

__global__ void hist_kernel(const int* __restrict__ dst) {
    int e = blockIdx.x * blockDim.x + threadIdx.x;
    if (e < N_EDGES) atomicAdd(&g_deg[dst[e]], 1);
}

// ---- multi-block exclusive scan over degrees (3 phases) ----
__global__ void scan_part1_kernel() {   // grid=SCAN_BLOCKS, 256 thr: block sums
    __shared__ int sh[256];
    int t = threadIdx.x;
    int i = blockIdx.x * 256 + t;
    sh[t] = (i < N_NODES) ? g_deg[i] : 0;
    __syncthreads();
    for (int off = 128; off > 0; off >>= 1) {
        if (t < off) sh[t] += sh[t + off];
        __syncthreads();
    }
    if (t == 0) g_blk[blockIdx.x] = sh[0];
}

__global__ void scan_part2_kernel() {   // 1 block, 256 thr: scan of 196 block sums
    __shared__ int sh[256];
    int t = threadIdx.x;
    int v = (t < SCAN_BLOCKS) ? g_blk[t] : 0;
    sh[t] = v;
    __syncthreads();
    for (int off = 1; off < 256; off <<= 1) {
        int u = (t >= off) ? sh[t - off] : 0;
        __syncthreads();
        sh[t] += u;
        __syncthreads();
    }
    if (t < SCAN_BLOCKS) g_blkoff[t] = sh[t] - v;   // exclusive
    if (t == SCAN_BLOCKS - 1) g_off[N_NODES] = sh[t];
}

__global__ void scan_part3_kernel() {   // grid=SCAN_BLOCKS, 256 thr: local scan + base
    __shared__ int sh[256];
    int t = threadIdx.x;
    int i = blockIdx.x * 256 + t;
    int d = (i < N_NODES) ? g_deg[i] : 0;
    sh[t] = d;
    __syncthreads();
    for (int off = 1; off < 256; off <<= 1) {
        int u = (t >= off) ? sh[t - off] : 0;
        __syncthreads();
        sh[t] += u;
        __syncthreads();
    }
    if (i < N_NODES) {
        int run = g_blkoff[blockIdx.x] + sh[t] - d;  // exclusive prefix
        g_off[i] = run;
        g_cur[i] = run;
        g_invdeg[i] = 1.0f / (float)max(d, 1);
    }
}

__global__ void scatter_kernel(const int* __restrict__ src, const int* __restrict__ dst) {
    int e = blockIdx.x * blockDim.x + threadIdx.x;
    if (e < N_EDGES) {
        int d = dst[e];
        int p = atomicAdd(&g_cur[d], 1);
        g_csr[p] = src[e];
    }
}

// ---------------- aggregation kernels (warp per node) ----------------
__global__ void gin_agg_kernel(const float* __restrict__ x) {
    int w = (blockIdx.x * blockDim.x + threadIdx.x) >> 5;
    int lane = threadIdx.x & 31;
    if (w >= N_NODES) return;
    const float4* x4 = (const float4*)x;
    float4 acc = __ldg(&x4[w * 32 + lane]);
    int e = g_off[w], end = g_off[w + 1];
    for (; e + 4 <= end; e += 4) {
        int s0 = g_csr[e + 0], s1 = g_csr[e + 1], s2 = g_csr[e + 2], s3 = g_csr[e + 3];
        float4 v0 = __ldg(&x4[s0 * 32 + lane]);
        float4 v1 = __ldg(&x4[s1 * 32 + lane]);
        float4 v2 = __ldg(&x4[s2 * 32 + lane]);
        float4 v3 = __ldg(&x4[s3 * 32 + lane]);
        acc.x += v0.x + v1.x + v2.x + v3.x;
        acc.y += v0.y + v1.y + v2.y + v3.y;
        acc.z += v0.z + v1.z + v2.z + v3.z;
        acc.w += v0.w + v1.w + v2.w + v3.w;
    }
    for (; e < end; e++) {
        int s0 = g_csr[e];
        float4 v0 = __ldg(&x4[s0 * 32 + lane]);
        acc.x += v0.x; acc.y += v0.y; acc.z += v0.z; acc.w += v0.w;
    }
    ((float4*)g_h0)[w * 32 + lane] = acc;
}

__device__ __forceinline__ float4 bn_relu4(float4 h, float4 sc, float4 sh) {
    float4 r;
    r.x = fmaxf(fmaf(h.x, sc.x, sh.x), 0.f);
    r.y = fmaxf(fmaf(h.y, sc.y, sh.y), 0.f);
    r.z = fmaxf(fmaf(h.z, sc.z, sh.z), 0.f);
    r.w = fmaxf(fmaf(h.w, sc.w, sh.w), 0.f);
    return r;
}

__global__ void sage_agg_kernel(const float* __restrict__ hraw,
                                float* __restrict__ hbn,
                                float* __restrict__ neigh) {
    int w = (blockIdx.x * blockDim.x + threadIdx.x) >> 5;
    int lane = threadIdx.x & 31;
    if (w >= N_NODES) return;
    float4 sc = *(const float4*)&g_scale[lane * 4];
    float4 sh = *(const float4*)&g_shift[lane * 4];
    const float4* h4 = (const float4*)hraw;

    float4 self = bn_relu4(__ldg(&h4[w * 32 + lane]), sc, sh);
    ((float4*)hbn)[w * 32 + lane] = self;

    float4 acc = make_float4(0.f, 0.f, 0.f, 0.f);
    int e = g_off[w], end = g_off[w + 1];
    for (; e + 4 <= end; e += 4) {
        int s0 = g_csr[e + 0], s1 = g_csr[e + 1], s2 = g_csr[e + 2], s3 = g_csr[e + 3];
        float4 v0 = bn_relu4(__ldg(&h4[s0 * 32 + lane]), sc, sh);
        float4 v1 = bn_relu4(__ldg(&h4[s1 * 32 + lane]), sc, sh);
        float4 v2 = bn_relu4(__ldg(&h4[s2 * 32 + lane]), sc, sh);
        float4 v3 = bn_relu4(__ldg(&h4[s3 * 32 + lane]), sc, sh);
        acc.x += v0.x + v1.x + v2.x + v3.x;
        acc.y += v0.y + v1.y + v2.y + v3.y;
        acc.z += v0.z + v1.z + v2.z + v3.z;
        acc.w += v0.w + v1.w + v2.w + v3.w;
    }
    for (; e < end; e++) {
        int s0 = g_csr[e];
        float4 v0 = bn_relu4(__ldg(&h4[s0 * 32 + lane]), sc, sh);
        acc.x += v0.x; acc.y += v0.y; acc.z += v0.z; acc.w += v0.w;
    }
    float id = g_invdeg[w];
    acc.x *= id; acc.y *= id; acc.z *= id; acc.w *= id;
    ((float4*)neigh)[w * 32 + lane] = acc;
}

// ---------------- shared GEMM building blocks ----------------
__device__ __forceinline__ void stage_A(float* Asf, const float* __restrict__ A,
                                        int rowBase, int kc, int M, int tid) {
#pragma unroll
    for (int i = 0; i < 4; i++) {
        int f = tid + 256 * i;
        int row = f >> 3, kq = f & 7;
        int grow = rowBase + row; if (grow >= M) grow = M - 1;
        float4 v = __ldg((const float4*)&A[grow * HID + kc + kq * 4]);
        int k0 = kq * 4;
        Asf[AS_IDX(k0 + 0, row)] = v.x;
        Asf[AS_IDX(k0 + 1, row)] = v.y;
        Asf[AS_IDX(k0 + 2, row)] = v.z;
        Asf[AS_IDX(k0 + 3, row)] = v.w;
    }
}

__device__ __forceinline__ void stage_B(float* Bsf, const float* __restrict__ W,
                                        int kc, int tid) {
#pragma unroll
    for (int i = 0; i < 4; i++) {
        int f = tid + 256 * i;
        int k = f >> 5, n4 = f & 31;
        float4 v = __ldg((const float4*)&W[(kc + k) * HID + n4 * 4]);
        *(float4*)&Bsf[BS_IDX(k, n4 * 4)] = v;
    }
}

__device__ __forceinline__ void compute_chunk(const float* __restrict__ Afrag,
                                              const float* __restrict__ Bsf,
                                              int trow, int tcol,
                                              unsigned long long acc[8][4]) {
#pragma unroll 8
    for (int k = 0; k < 32; k++) {
        const float* ar = &Afrag[k * 132 + 4 * (k >> 2) + trow * 16];
        unsigned long long a[8];
        ulonglong2 t;
        t = *(const ulonglong2*)(ar + 0);  a[0] = t.x; a[1] = t.y;
        t = *(const ulonglong2*)(ar + 4);  a[2] = t.x; a[3] = t.y;
        t = *(const ulonglong2*)(ar + 8);  a[4] = t.x; a[5] = t.y;
        t = *(const ulonglong2*)(ar + 12); a[6] = t.x; a[7] = t.y;
        float4 b4 = *(const float4*)&Bsf[BS_IDX(k, tcol * 4)];
        unsigned long long bb0 = pack_dup(b4.x);
        unsigned long long bb1 = pack_dup(b4.y);
        unsigned long long bb2 = pack_dup(b4.z);
        unsigned long long bb3 = pack_dup(b4.w);
#pragma unroll
        for (int r = 0; r < 8; r++) {
            asm("fma.rn.f32x2 %0,%1,%2,%0;" : "+l"(acc[r][0]) : "l"(a[r]), "l"(bb0));
            asm("fma.rn.f32x2 %0,%1,%2,%0;" : "+l"(acc[r][1]) : "l"(a[r]), "l"(bb1));
            asm("fma.rn.f32x2 %0,%1,%2,%0;" : "+l"(acc[r][2]) : "l"(a[r]), "l"(bb2));
            asm("fma.rn.f32x2 %0,%1,%2,%0;" : "+l"(acc[r][3]) : "l"(a[r]), "l"(bb3));
        }
    }
}

__device__ __forceinline__ void gemm_epilogue(unsigned long long acc[8][4],
                                              const float* __restrict__ bias,
                                              float* __restrict__ out,
                                              float* csum, float* csq,
                                              int rowBase, int trow, int tcol,
                                              int M, int do_relu, int do_stats, int tid) {
    float4 bias4 = __ldg((const float4*)&bias[tcol * 4]);
    float bv[4] = { bias4.x, bias4.y, bias4.z, bias4.w };
    float lsum[4] = {0, 0, 0, 0}, lsq[4] = {0, 0, 0, 0};
#pragma unroll
    for (int r = 0; r < 8; r++) {
        float vlo[4], vhi[4];
#pragma unroll
        for (int c = 0; c < 4; c++) {
            unsigned long long u = acc[r][c];
            vlo[c] = __uint_as_float((unsigned)u) + bv[c];
            vhi[c] = __uint_as_float((unsigned)(u >> 32)) + bv[c];
            if (do_relu) { vlo[c] = fmaxf(vlo[c], 0.f); vhi[c] = fmaxf(vhi[c], 0.f); }
        }
        int row0 = rowBase + trow * 16 + 2 * r;
        if (row0 < M) {
            *(float4*)&out[row0 * HID + tcol * 4] = make_float4(vlo[0], vlo[1], vlo[2], vlo[3]);
            if (do_stats)
#pragma unroll
                for (int c = 0; c < 4; c++) { lsum[c] += vlo[c]; lsq[c] += vlo[c] * vlo[c]; }
        }
        if (row0 + 1 < M) {
            *(float4*)&out[(row0 + 1) * HID + tcol * 4] = make_float4(vhi[0], vhi[1], vhi[2], vhi[3]);
            if (do_stats)
#pragma unroll
                for (int c = 0; c < 4; c++) { lsum[c] += vhi[c]; lsq[c] += vhi[c] * vhi[c]; }
        }
    }
    if (do_stats) {
#pragma unroll
        for (int c = 0; c < 4; c++) {
            atomicAdd(&csum[tcol * 4 + c], lsum[c]);
            atomicAdd(&csq[tcol * 4 + c], lsq[c]);
        }
        __syncthreads();
        if (tid < HID) {
            atomicAdd(&g_bnsum[tid], csum[tid]);
            atomicAdd(&g_bnsq[tid], csq[tid]);
        }
    }
}

// ---------------- SAGE GEMM: out = A1@W1 + A2@W2 + bias, stats ----------------
__global__ __launch_bounds__(256, 2) void gemm_sage_kernel(
    const float* __restrict__ A1, const float* __restrict__ W1,
    const float* __restrict__ A2, const float* __restrict__ W2,
    const float* __restrict__ bias, float* __restrict__ out, int M)
{
    __shared__ __align__(16) float Asf[AS_SIZE];
    __shared__ __align__(16) float Bsf[BS_SIZE];
    __shared__ float csum[HID], csq[HID];

    int tid = threadIdx.x;
    int tcol = tid & 31;
    int trow = tid >> 5;
    int rowBase = blockIdx.x * 128;

    unsigned long long acc[8][4];
#pragma unroll
    for (int r = 0; r < 8; r++)
#pragma unroll
        for (int c = 0; c < 4; c++) acc[r][c] = 0ULL;
    if (tid < HID) { csum[tid] = 0.f; csq[tid] = 0.f; }

    for (int part = 0; part < 2; part++) {
        const float* A = part ? A2 : A1;
        const float* W = part ? W2 : W1;
        for (int kc = 0; kc < HID; kc += 32) {
            __syncthreads();
            stage_A(Asf, A, rowBase, kc, M, tid);
            stage_B(Bsf, W, kc, tid);
            __syncthreads();
            compute_chunk(Asf, Bsf, trow, tcol, acc);
        }
    }
    gemm_epilogue(acc, bias, out, csum, csq, rowBase, trow, tcol, M, 0, 1, tid);
}

// ---------------- fused GIN MLP: out = relu(A@W1+b1)@W2 + b2 (+stats) ----------------
__global__ __launch_bounds__(256, 2) void gin_mlp_fused_kernel(
    const float* __restrict__ A, const float* __restrict__ W1, const float* __restrict__ b1,
    const float* __restrict__ W2, const float* __restrict__ b2,
    float* __restrict__ out, int M)
{
    extern __shared__ __align__(16) float dyn[];
    float* Asf = dyn;
    float* Bsf = dyn + AS_SIZE;
    float* Tsf = dyn + AS_SIZE + BS_SIZE;
    __shared__ float csum[HID], csq[HID];

    int tid = threadIdx.x;
    int tcol = tid & 31;
    int trow = tid >> 5;
    int rowBase = blockIdx.x * 128;

    unsigned long long acc[8][4];
#pragma unroll
    for (int r = 0; r < 8; r++)
#pragma unroll
        for (int c = 0; c < 4; c++) acc[r][c] = 0ULL;
    if (tid < HID) { csum[tid] = 0.f; csq[tid] = 0.f; }

    // ---- phase 1: t = relu(A @ W1 + b1) ----
    for (int kc = 0; kc < HID; kc += 32) {
        __syncthreads();
        stage_A(Asf, A, rowBase, kc, M, tid);
        stage_B(Bsf, W1, kc, tid);
        __syncthreads();
        compute_chunk(Asf, Bsf, trow, tcol, acc);
    }

    // write t into Tsf in transposed A-frag layout; reset acc
    {
        float4 bias4 = __ldg((const float4*)&b1[tcol * 4]);
        float bv[4] = { bias4.x, bias4.y, bias4.z, bias4.w };
        __syncthreads();
#pragma unroll
        for (int r = 0; r < 8; r++) {
            int row0 = trow * 16 + 2 * r;
#pragma unroll
            for (int c = 0; c < 4; c++) {
                unsigned long long u = acc[r][c];
                float vlo = fmaxf(__uint_as_float((unsigned)u) + bv[c], 0.f);
                float vhi = fmaxf(__uint_as_float((unsigned)(u >> 32)) + bv[c], 0.f);
                int col = tcol * 4 + c;
                Tsf[AS_IDX(col, row0)] = vlo;
                Tsf[AS_IDX(col, row0 + 1)] = vhi;
                acc[r][c] = 0ULL;
            }
        }
    }
    __syncthreads();

    // ---- phase 2: out = t @ W2 + b2, with BN stats ----
    for (int kc = 0; kc < HID; kc += 32) {
        __syncthreads();
        stage_B(Bsf, W2, kc, tid);
        __syncthreads();
        compute_chunk(&Tsf[AS_IDX(kc, 0)], Bsf, trow, tcol, acc);
    }
    gemm_epilogue(acc, b2, out, csum, csq, rowBase, trow, tcol, M, 0, 1, tid);
}

// ---------------- BN finalize ----------------
__global__ void bn_finalize_kernel(const float* __restrict__ gamma, const float* __restrict__ beta) {
    int c = threadIdx.x;
    const float invn = 1.0f / (float)N_NODES;
    float m = g_bnsum[c] * invn;
    float var = g_bnsq[c] * invn - m * m;
    var = fmaxf(var, 0.f);
    float s = gamma[c] * rsqrtf(var + BN_EPS);
    g_scale[c] = s;
    g_shift[c] = beta[c] - m * s;
    g_bnsum[c] = 0.f;
    g_bnsq[c] = 0.f;
}

// ---------------- pooling: batch is sorted, block per graph ----------------
__device__ __forceinline__ int lbound(const int* a, int n, int v) {
    int lo = 0, hi = n;
    while (lo < hi) {
        int mid = (lo + hi) >> 1;
        if (a[mid] < v) lo = mid + 1; else hi = mid;
    }
    return lo;
}

__global__ void pool_kernel(const float* __restrict__ hraw,
                            const int* __restrict__ batch,
                            float* __restrict__ out) {
    int gg = blockIdx.x;
    int c = threadIdx.x;
    int start = lbound(batch, N_NODES, gg);
    int end = lbound(batch, N_NODES, gg + 1);
    int cnt = end - start;
    float sc = g_scale[c], sh = g_shift[c];
    float s = 0.f;
    for (int i = start; i < end; i++) {
        float v = fmaf(hraw[i * HID + c], sc, sh);
        s += fmaxf(v, 0.f);
    }
    out[gg * HID + c] = s / fmaxf((float)cnt, 1.f);
}

// ---------------- launch ----------------
extern "C" void kernel_launch(void* const* d_in, const int* in_sizes, int n_in,
                              void* d_out, int out_size) {
    (void)in_sizes; (void)n_in; (void)out_size;
    const float* x       = (const float*)d_in[0];
    const int*   eidx    = (const int*)d_in[1];
    const int*   batch   = (const int*)d_in[2];
    const float* gin_w1  = (const float*)d_in[3];
    const float* gin_b1  = (const float*)d_in[4];
    const float* gin_w2  = (const float*)d_in[5];
    const float* gin_b2  = (const float*)d_in[6];
    const float* sage_wl = (const float*)d_in[7];
    const float* sage_bl = (const float*)d_in[8];
    const float* sage_wr = (const float*)d_in[9];
    const float* bn_g    = (const float*)d_in[10];
    const float* bn_b    = (const float*)d_in[11];
    float* out = (float*)d_out;

    const int* src = eidx;
    const int* dst = eidx + N_EDGES;

    float *p_h0, *p_h1, *p_hbn, *p_ng, *p_t2;
    cudaGetSymbolAddress((void**)&p_h0, g_h0);
    cudaGetSymbolAddress((void**)&p_h1, g_h1);
    cudaGetSymbolAddress((void**)&p_hbn, g_hbn);
    cudaGetSymbolAddress((void**)&p_ng, g_neigh);
    cudaGetSymbolAddress((void**)&p_t2, g_t2);

    const int M = N_NODES;
    const int gemmGrid = (M + 127) / 128;            // 391
    const int aggGrid = (N_NODES * 32 + 255) / 256;  // warp per node
    const int edgeGrid = (N_EDGES + 255) / 256;

    const int fusedSmem = (AS_SIZE + BS_SIZE + TS_SIZE) * 4;  // ~102KB
    static int attr_set = 0;
    if (!attr_set) {
        cudaFuncSetAttribute(gin_mlp_fused_kernel,
                             cudaFuncAttributeMaxDynamicSharedMemorySize, fusedSmem);
        attr_set = 1;
    }

    // CSR build (multi-block scan)
    zero_init_kernel<<<(N_NODES + 255) / 256, 256>>>();
    hist_kernel<<<edgeGrid, 256>>>(dst);
    scan_part1_kernel<<<SCAN_BLOCKS, 256>>>();
    scan_part2_kernel<<<1, 256>>>();
    scan_part3_kernel<<<SCAN_BLOCKS, 256>>>();
    scatter_kernel<<<edgeGrid, 256>>>(src, dst);

    // Layer 0: GIN (fused MLP)
    gin_agg_kernel<<<aggGrid, 256>>>(x);
    gin_mlp_fused_kernel<<<gemmGrid, 256, fusedSmem>>>(p_h0, gin_w1, gin_b1, gin_w2, gin_b2, p_h1, M);
    bn_finalize_kernel<<<1, HID>>>(bn_g + 0 * HID, bn_b + 0 * HID);

    // SAGE layer 0
    sage_agg_kernel<<<aggGrid, 256>>>(p_h1, p_hbn, p_ng);
    gemm_sage_kernel<<<gemmGrid, 256>>>(p_ng, sage_wl, p_hbn, sage_wr, sage_bl, p_h0, M);
    bn_finalize_kernel<<<1, HID>>>(bn_g + 1 * HID, bn_b + 1 * HID);

    // SAGE layer 1
    sage_agg_kernel<<<aggGrid, 256>>>(p_h0, p_hbn, p_ng);
    gemm_sage_kernel<<<gemmGrid, 256>>>(p_ng, sage_wl + HID * HID, p_hbn, sage_wr + HID * HID,
                                        sage_bl + HID, p_t2, M);
    bn_finalize_kernel<<<1, HID>>>(bn_g + 2 * HID, bn_b + 2 * HID);

    // global mean pool (batch sorted)
    pool_kernel<<<N_GRAPHS, HID>>>(p_t2, batch, out);
}

// round 8
// speedup vs baseline: 1.3901x; 1.0231x over previous
#include <cuda_runtime.h>
#include <cuda_bf16.h>
#include <cstdint>

#define N_NODES 50000
#define N_EDGES 600000
#define HID     128
#define N_GRAPHS 512
#define BN_EPS  1e-5f
#define SCAN_BLOCKS ((N_NODES + 255) / 256)   // 196

// ---------------- scratch ----------------
__device__ float g_h0[N_NODES * HID];
__device__ float g_h1[N_NODES * HID];
__device__ float g_hbn[N_NODES * HID];
__device__ float g_neigh[N_NODES * HID];
__device__ float g_t2[N_NODES * HID];

__device__ int   g_deg[N_NODES];
__device__ int   g_off[N_NODES + 1];
__device__ int   g_cur[N_NODES];
__device__ int   g_csr[N_EDGES];
__device__ float g_invdeg[N_NODES];
__device__ int   g_blk[SCAN_BLOCKS];
__device__ int   g_blkoff[SCAN_BLOCKS];

__device__ float g_bnsum[3 * HID];   // per-layer BN stats
__device__ float g_bnsq[3 * HID];

// ---------------- helpers ----------------
__device__ __forceinline__ unsigned long long pack_dup(float x) {
    unsigned long long d;
    asm("mov.b64 %0,{%1,%1};" : "=l"(d) : "f"(x));
    return d;
}

// 128-row transposed A layout (GIN kernel): (k,row) at k*132 + 4*(k>>2) + row
#define AS_IDX(k, row) ((k) * 132 + 4 * ((k) >> 2) + (row))
#define AS_SIZE 4256
// 64-row transposed A layout (SAGE kernel)
#define AS64_IDX(k, row) ((k) * 68 + 4 * ((k) >> 2) + (row))
#define AS64_SIZE 2208
// B layout: (k,n) at k*132 + n
#define BS_IDX(k, n) ((k) * 132 + (n))
#define BS_SIZE 4224
#define TS_SIZE 17024

// ---------------- setup kernels ----------------
__global__ void zero_init_kernel() {
    int i = blockIdx.x * blockDim.x + threadIdx.x;
    if (i < N_NODES) g_deg[i] = 0;
    if (i < 3 * HID) { g_bnsum[i] = 0.f; g_bnsq[i] = 0.f; }
}

__global__ void hist_kernel(const int* __restrict__ dst) {
    int e = blockIdx.x * blockDim.x + threadIdx.x;
    if (e < N_EDGES) atomicAdd(&g_deg[dst[e]], 1);
}

__global__ void scan_part1_kernel() {
    __shared__ int sh[256];
    int t = threadIdx.x;
    int i = blockIdx.x * 256 + t;
    sh[t] = (i < N_NODES) ? g_deg[i] : 0;
    __syncthreads();
    for (int off = 128; off > 0; off >>= 1) {
        if (t < off) sh[t] += sh[t + off];
        __syncthreads();
    }
    if (t == 0) g_blk[blockIdx.x] = sh[0];
}

__global__ void scan_part2_kernel() {
    __shared__ int sh[256];
    int t = threadIdx.x;
    int v = (t < SCAN_BLOCKS) ? g_blk[t] : 0;
    sh[t] = v;
    __syncthreads();
    for (int off = 1; off < 256; off <<= 1) {
        int u = (t >= off) ? sh[t - off] : 0;
        __syncthreads();
        sh[t] += u;
        __syncthreads();
    }
    if (t < SCAN_BLOCKS) g_blkoff[t] = sh[t] - v;
    if (t == SCAN_BLOCKS - 1) g_off[N_NODES] = sh[t];
}

__global__ void scan_part3_kernel() {
    __shared__ int sh[256];
    int t = threadIdx.x;
    int i = blockIdx.x * 256 + t;
    int d = (i < N_NODES) ? g_deg[i] : 0;
    sh[t] = d;
    __syncthreads();
    for (int off = 1; off < 256; off <<= 1) {
        int u = (t >= off) ? sh[t - off] : 0;
        __syncthreads();
        sh[t] += u;
        __syncthreads();
    }
    if (i < N_NODES) {
        int run = g_blkoff[blockIdx.x] + sh[t] - d;
        g_off[i] = run;
        g_cur[i] = run;
        g_invdeg[i] = 1.0f / (float)max(d, 1);
    }
}

__global__ void scatter_kernel(const int* __restrict__ src, const int* __restrict__ dst) {
    int e = blockIdx.x * blockDim.x + threadIdx.x;
    if (e < N_EDGES) {
        int d = dst[e];
        int p = atomicAdd(&g_cur[d], 1);
        g_csr[p] = src[e];
    }
}

// ---------------- aggregation kernels (warp per node) ----------------
__global__ void gin_agg_kernel(const float* __restrict__ x) {
    int w = (blockIdx.x * blockDim.x + threadIdx.x) >> 5;
    int lane = threadIdx.x & 31;
    if (w >= N_NODES) return;
    const float4* x4 = (const float4*)x;
    float4 acc = __ldg(&x4[w * 32 + lane]);
    int e = g_off[w], end = g_off[w + 1];
    for (; e + 4 <= end; e += 4) {
        int s0 = g_csr[e + 0], s1 = g_csr[e + 1], s2 = g_csr[e + 2], s3 = g_csr[e + 3];
        float4 v0 = __ldg(&x4[s0 * 32 + lane]);
        float4 v1 = __ldg(&x4[s1 * 32 + lane]);
        float4 v2 = __ldg(&x4[s2 * 32 + lane]);
        float4 v3 = __ldg(&x4[s3 * 32 + lane]);
        acc.x += v0.x + v1.x + v2.x + v3.x;
        acc.y += v0.y + v1.y + v2.y + v3.y;
        acc.z += v0.z + v1.z + v2.z + v3.z;
        acc.w += v0.w + v1.w + v2.w + v3.w;
    }
    for (; e < end; e++) {
        int s0 = g_csr[e];
        float4 v0 = __ldg(&x4[s0 * 32 + lane]);
        acc.x += v0.x; acc.y += v0.y; acc.z += v0.z; acc.w += v0.w;
    }
    ((float4*)g_h0)[w * 32 + lane] = acc;
}

__device__ __forceinline__ float4 bn_relu4(float4 h, float4 sc, float4 sh) {
    float4 r;
    r.x = fmaxf(fmaf(h.x, sc.x, sh.x), 0.f);
    r.y = fmaxf(fmaf(h.y, sc.y, sh.y), 0.f);
    r.z = fmaxf(fmaf(h.z, sc.z, sh.z), 0.f);
    r.w = fmaxf(fmaf(h.w, sc.w, sh.w), 0.f);
    return r;
}

// compute BN scale/shift for 4 channels from raw stats (inline finalize)
__device__ __forceinline__ void bn_coeffs(int layer, int c0,
                                          const float* __restrict__ gamma,
                                          const float* __restrict__ beta,
                                          float4& sc, float4& sh) {
    const float invn = 1.0f / (float)N_NODES;
    float4 s1 = *(const float4*)&g_bnsum[layer * HID + c0];
    float4 s2 = *(const float4*)&g_bnsq[layer * HID + c0];
    float4 gm = __ldg((const float4*)&gamma[c0]);
    float4 bt = __ldg((const float4*)&beta[c0]);
    float m, var;
    m = s1.x * invn; var = fmaxf(s2.x * invn - m * m, 0.f);
    sc.x = gm.x * rsqrtf(var + BN_EPS); sh.x = bt.x - m * sc.x;
    m = s1.y * invn; var = fmaxf(s2.y * invn - m * m, 0.f);
    sc.y = gm.y * rsqrtf(var + BN_EPS); sh.y = bt.y - m * sc.y;
    m = s1.z * invn; var = fmaxf(s2.z * invn - m * m, 0.f);
    sc.z = gm.z * rsqrtf(var + BN_EPS); sh.z = bt.z - m * sc.z;
    m = s1.w * invn; var = fmaxf(s2.w * invn - m * m, 0.f);
    sc.w = gm.w * rsqrtf(var + BN_EPS); sh.w = bt.w - m * sc.w;
}

__global__ void sage_agg_kernel(const float* __restrict__ hraw,
                                float* __restrict__ hbn,
                                float* __restrict__ neigh,
                                const float* __restrict__ gamma,
                                const float* __restrict__ beta,
                                int layer) {
    int w = (blockIdx.x * blockDim.x + threadIdx.x) >> 5;
    int lane = threadIdx.x & 31;
    if (w >= N_NODES) return;
    float4 sc, sh;
    bn_coeffs(layer, lane * 4, gamma, beta, sc, sh);
    const float4* h4 = (const float4*)hraw;

    float4 self = bn_relu4(__ldg(&h4[w * 32 + lane]), sc, sh);
    ((float4*)hbn)[w * 32 + lane] = self;

    float4 acc = make_float4(0.f, 0.f, 0.f, 0.f);
    int e = g_off[w], end = g_off[w + 1];
    for (; e + 4 <= end; e += 4) {
        int s0 = g_csr[e + 0], s1 = g_csr[e + 1], s2 = g_csr[e + 2], s3 = g_csr[e + 3];
        float4 v0 = bn_relu4(__ldg(&h4[s0 * 32 + lane]), sc, sh);
        float4 v1 = bn_relu4(__ldg(&h4[s1 * 32 + lane]), sc, sh);
        float4 v2 = bn_relu4(__ldg(&h4[s2 * 32 + lane]), sc, sh);
        float4 v3 = bn_relu4(__ldg(&h4[s3 * 32 + lane]), sc, sh);
        acc.x += v0.x + v1.x + v2.x + v3.x;
        acc.y += v0.y + v1.y + v2.y + v3.y;
        acc.z += v0.z + v1.z + v2.z + v3.z;
        acc.w += v0.w + v1.w + v2.w + v3.w;
    }
    for (; e < end; e++) {
        int s0 = g_csr[e];
        float4 v0 = bn_relu4(__ldg(&h4[s0 * 32 + lane]), sc, sh);
        acc.x += v0.x; acc.y += v0.y; acc.z += v0.z; acc.w += v0.w;
    }
    float id = g_invdeg[w];
    acc.x *= id; acc.y *= id; acc.z *= id; acc.w *= id;
    ((float4*)neigh)[w * 32 + lane] = acc;
}

// ---------------- GEMM building blocks ----------------
// 128-row staging (GIN)
__device__ __forceinline__ void stage_A(float* Asf, const float* __restrict__ A,
                                        int rowBase, int kc, int M, int tid) {
#pragma unroll
    for (int i = 0; i < 4; i++) {
        int f = tid + 256 * i;
        int row = f >> 3, kq = f & 7;
        int grow = rowBase + row; if (grow >= M) grow = M - 1;
        float4 v = __ldg((const float4*)&A[grow * HID + kc + kq * 4]);
        int k0 = kq * 4;
        Asf[AS_IDX(k0 + 0, row)] = v.x;
        Asf[AS_IDX(k0 + 1, row)] = v.y;
        Asf[AS_IDX(k0 + 2, row)] = v.z;
        Asf[AS_IDX(k0 + 3, row)] = v.w;
    }
}

// 64-row staging (SAGE)
__device__ __forceinline__ void stage_A64(float* Asf, const float* __restrict__ A,
                                          int rowBase, int kc, int M, int tid) {
#pragma unroll
    for (int i = 0; i < 2; i++) {
        int f = tid + 256 * i;   // 0..511
        int row = f >> 3, kq = f & 7;
        int grow = rowBase + row; if (grow >= M) grow = M - 1;
        float4 v = __ldg((const float4*)&A[grow * HID + kc + kq * 4]);
        int k0 = kq * 4;
        Asf[AS64_IDX(k0 + 0, row)] = v.x;
        Asf[AS64_IDX(k0 + 1, row)] = v.y;
        Asf[AS64_IDX(k0 + 2, row)] = v.z;
        Asf[AS64_IDX(k0 + 3, row)] = v.w;
    }
}

__device__ __forceinline__ void stage_B(float* Bsf, const float* __restrict__ W,
                                        int kc, int tid) {
#pragma unroll
    for (int i = 0; i < 4; i++) {
        int f = tid + 256 * i;
        int k = f >> 5, n4 = f & 31;
        float4 v = __ldg((const float4*)&W[(kc + k) * HID + n4 * 4]);
        *(float4*)&Bsf[BS_IDX(k, n4 * 4)] = v;
    }
}

// 128-row compute (GIN)
__device__ __forceinline__ void compute_chunk(const float* __restrict__ Afrag,
                                              const float* __restrict__ Bsf,
                                              int trow, int tcol,
                                              unsigned long long acc[8][4]) {
#pragma unroll 8
    for (int k = 0; k < 32; k++) {
        const float* ar = &Afrag[k * 132 + 4 * (k >> 2) + trow * 16];
        unsigned long long a[8];
        ulonglong2 t;
        t = *(const ulonglong2*)(ar + 0);  a[0] = t.x; a[1] = t.y;
        t = *(const ulonglong2*)(ar + 4);  a[2] = t.x; a[3] = t.y;
        t = *(const ulonglong2*)(ar + 8);  a[4] = t.x; a[5] = t.y;
        t = *(const ulonglong2*)(ar + 12); a[6] = t.x; a[7] = t.y;
        float4 b4 = *(const float4*)&Bsf[BS_IDX(k, tcol * 4)];
        unsigned long long bb0 = pack_dup(b4.x);
        unsigned long long bb1 = pack_dup(b4.y);
        unsigned long long bb2 = pack_dup(b4.z);
        unsigned long long bb3 = pack_dup(b4.w);
#pragma unroll
        for (int r = 0; r < 8; r++) {
            asm("fma.rn.f32x2 %0,%1,%2,%0;" : "+l"(acc[r][0]) : "l"(a[r]), "l"(bb0));
            asm("fma.rn.f32x2 %0,%1,%2,%0;" : "+l"(acc[r][1]) : "l"(a[r]), "l"(bb1));
            asm("fma.rn.f32x2 %0,%1,%2,%0;" : "+l"(acc[r][2]) : "l"(a[r]), "l"(bb2));
            asm("fma.rn.f32x2 %0,%1,%2,%0;" : "+l"(acc[r][3]) : "l"(a[r]), "l"(bb3));
        }
    }
}

// 64-row compute (SAGE)
__device__ __forceinline__ void compute_chunk64(const float* __restrict__ Afrag,
                                                const float* __restrict__ Bsf,
                                                int trow, int tcol,
                                                unsigned long long acc[4][4]) {
#pragma unroll 8
    for (int k = 0; k < 32; k++) {
        const float* ar = &Afrag[k * 68 + 4 * (k >> 2) + trow * 8];
        unsigned long long a[4];
        ulonglong2 t;
        t = *(const ulonglong2*)(ar + 0); a[0] = t.x; a[1] = t.y;
        t = *(const ulonglong2*)(ar + 4); a[2] = t.x; a[3] = t.y;
        float4 b4 = *(const float4*)&Bsf[BS_IDX(k, tcol * 4)];
        unsigned long long bb0 = pack_dup(b4.x);
        unsigned long long bb1 = pack_dup(b4.y);
        unsigned long long bb2 = pack_dup(b4.z);
        unsigned long long bb3 = pack_dup(b4.w);
#pragma unroll
        for (int r = 0; r < 4; r++) {
            asm("fma.rn.f32x2 %0,%1,%2,%0;" : "+l"(acc[r][0]) : "l"(a[r]), "l"(bb0));
            asm("fma.rn.f32x2 %0,%1,%2,%0;" : "+l"(acc[r][1]) : "l"(a[r]), "l"(bb1));
            asm("fma.rn.f32x2 %0,%1,%2,%0;" : "+l"(acc[r][2]) : "l"(a[r]), "l"(bb2));
            asm("fma.rn.f32x2 %0,%1,%2,%0;" : "+l"(acc[r][3]) : "l"(a[r]), "l"(bb3));
        }
    }
}

// 128-row epilogue (GIN): bias + store + stats into layer arrays
__device__ __forceinline__ void gemm_epilogue(unsigned long long acc[8][4],
                                              const float* __restrict__ bias,
                                              float* __restrict__ out,
                                              float* csum, float* csq,
                                              float* statS, float* statQ,
                                              int rowBase, int trow, int tcol,
                                              int M, int tid) {
    float4 bias4 = __ldg((const float4*)&bias[tcol * 4]);
    float bv[4] = { bias4.x, bias4.y, bias4.z, bias4.w };
    float lsum[4] = {0, 0, 0, 0}, lsq[4] = {0, 0, 0, 0};
#pragma unroll
    for (int r = 0; r < 8; r++) {
        float vlo[4], vhi[4];
#pragma unroll
        for (int c = 0; c < 4; c++) {
            unsigned long long u = acc[r][c];
            vlo[c] = __uint_as_float((unsigned)u) + bv[c];
            vhi[c] = __uint_as_float((unsigned)(u >> 32)) + bv[c];
        }
        int row0 = rowBase + trow * 16 + 2 * r;
        if (row0 < M) {
            *(float4*)&out[row0 * HID + tcol * 4] = make_float4(vlo[0], vlo[1], vlo[2], vlo[3]);
#pragma unroll
            for (int c = 0; c < 4; c++) { lsum[c] += vlo[c]; lsq[c] += vlo[c] * vlo[c]; }
        }
        if (row0 + 1 < M) {
            *(float4*)&out[(row0 + 1) * HID + tcol * 4] = make_float4(vhi[0], vhi[1], vhi[2], vhi[3]);
#pragma unroll
            for (int c = 0; c < 4; c++) { lsum[c] += vhi[c]; lsq[c] += vhi[c] * vhi[c]; }
        }
    }
#pragma unroll
    for (int c = 0; c < 4; c++) {
        atomicAdd(&csum[tcol * 4 + c], lsum[c]);
        atomicAdd(&csq[tcol * 4 + c], lsq[c]);
    }
    __syncthreads();
    if (tid < HID) {
        atomicAdd(&statS[tid], csum[tid]);
        atomicAdd(&statQ[tid], csq[tid]);
    }
}

// ---------------- SAGE GEMM: 64-row tiles, occupancy 4 ----------------
__global__ __launch_bounds__(256, 4) void gemm_sage_kernel(
    const float* __restrict__ A1, const float* __restrict__ W1,
    const float* __restrict__ A2, const float* __restrict__ W2,
    const float* __restrict__ bias, float* __restrict__ out,
    float* __restrict__ statS, float* __restrict__ statQ, int M)
{
    __shared__ __align__(16) float Asf[AS64_SIZE];
    __shared__ __align__(16) float Bsf[BS_SIZE];
    __shared__ float csum[HID], csq[HID];

    int tid = threadIdx.x;
    int tcol = tid & 31;
    int trow = tid >> 5;
    int rowBase = blockIdx.x * 64;

    unsigned long long acc[4][4];
#pragma unroll
    for (int r = 0; r < 4; r++)
#pragma unroll
        for (int c = 0; c < 4; c++) acc[r][c] = 0ULL;
    if (tid < HID) { csum[tid] = 0.f; csq[tid] = 0.f; }

    for (int part = 0; part < 2; part++) {
        const float* A = part ? A2 : A1;
        const float* W = part ? W2 : W1;
        for (int kc = 0; kc < HID; kc += 32) {
            __syncthreads();
            stage_A64(Asf, A, rowBase, kc, M, tid);
            stage_B(Bsf, W, kc, tid);
            __syncthreads();
            compute_chunk64(Asf, Bsf, trow, tcol, acc);
        }
    }

    // epilogue (64-row)
    float4 bias4 = __ldg((const float4*)&bias[tcol * 4]);
    float bv[4] = { bias4.x, bias4.y, bias4.z, bias4.w };
    float lsum[4] = {0, 0, 0, 0}, lsq[4] = {0, 0, 0, 0};
#pragma unroll
    for (int r = 0; r < 4; r++) {
        float vlo[4], vhi[4];
#pragma unroll
        for (int c = 0; c < 4; c++) {
            unsigned long long u = acc[r][c];
            vlo[c] = __uint_as_float((unsigned)u) + bv[c];
            vhi[c] = __uint_as_float((unsigned)(u >> 32)) + bv[c];
        }
        int row0 = rowBase + trow * 8 + 2 * r;
        if (row0 < M) {
            *(float4*)&out[row0 * HID + tcol * 4] = make_float4(vlo[0], vlo[1], vlo[2], vlo[3]);
#pragma unroll
            for (int c = 0; c < 4; c++) { lsum[c] += vlo[c]; lsq[c] += vlo[c] * vlo[c]; }
        }
        if (row0 + 1 < M) {
            *(float4*)&out[(row0 + 1) * HID + tcol * 4] = make_float4(vhi[0], vhi[1], vhi[2], vhi[3]);
#pragma unroll
            for (int c = 0; c < 4; c++) { lsum[c] += vhi[c]; lsq[c] += vhi[c] * vhi[c]; }
        }
    }
#pragma unroll
    for (int c = 0; c < 4; c++) {
        atomicAdd(&csum[tcol * 4 + c], lsum[c]);
        atomicAdd(&csq[tcol * 4 + c], lsq[c]);
    }
    __syncthreads();
    if (tid < HID) {
        atomicAdd(&statS[tid], csum[tid]);
        atomicAdd(&statQ[tid], csq[tid]);
    }
}

// ---------------- fused GIN MLP (128-row tiles, occ 2) ----------------
__global__ __launch_bounds__(256, 2) void gin_mlp_fused_kernel(
    const float* __restrict__ A, const float* __restrict__ W1, const float* __restrict__ b1,
    const float* __restrict__ W2, const float* __restrict__ b2,
    float* __restrict__ out, float* __restrict__ statS, float* __restrict__ statQ, int M)
{
    extern __shared__ __align__(16) float dyn[];
    float* Asf = dyn;
    float* Bsf = dyn + AS_SIZE;
    float* Tsf = dyn + AS_SIZE + BS_SIZE;
    __shared__ float csum[HID], csq[HID];

    int tid = threadIdx.x;
    int tcol = tid & 31;
    int trow = tid >> 5;
    int rowBase = blockIdx.x * 128;

    unsigned long long acc[8][4];
#pragma unroll
    for (int r = 0; r < 8; r++)
#pragma unroll
        for (int c = 0; c < 4; c++) acc[r][c] = 0ULL;
    if (tid < HID) { csum[tid] = 0.f; csq[tid] = 0.f; }

    for (int kc = 0; kc < HID; kc += 32) {
        __syncthreads();
        stage_A(Asf, A, rowBase, kc, M, tid);
        stage_B(Bsf, W1, kc, tid);
        __syncthreads();
        compute_chunk(Asf, Bsf, trow, tcol, acc);
    }

    {
        float4 bias4 = __ldg((const float4*)&b1[tcol * 4]);
        float bv[4] = { bias4.x, bias4.y, bias4.z, bias4.w };
        __syncthreads();
#pragma unroll
        for (int r = 0; r < 8; r++) {
            int row0 = trow * 16 + 2 * r;
#pragma unroll
            for (int c = 0; c < 4; c++) {
                unsigned long long u = acc[r][c];
                float vlo = fmaxf(__uint_as_float((unsigned)u) + bv[c], 0.f);
                float vhi = fmaxf(__uint_as_float((unsigned)(u >> 32)) + bv[c], 0.f);
                int col = tcol * 4 + c;
                Tsf[AS_IDX(col, row0)] = vlo;
                Tsf[AS_IDX(col, row0 + 1)] = vhi;
                acc[r][c] = 0ULL;
            }
        }
    }
    __syncthreads();

    for (int kc = 0; kc < HID; kc += 32) {
        __syncthreads();
        stage_B(Bsf, W2, kc, tid);
        __syncthreads();
        compute_chunk(&Tsf[AS_IDX(kc, 0)], Bsf, trow, tcol, acc);
    }
    gemm_epilogue(acc, b2, out, csum, csq, statS, statQ, rowBase, trow, tcol, M, tid);
}

// ---------------- pooling (inline BN finalize for last layer) ----------------
__device__ __forceinline__ int lbound(const int* a, int n, int v) {
    int lo = 0, hi = n;
    while (lo < hi) {
        int mid = (lo + hi) >> 1;
        if (a[mid] < v) lo = mid + 1; else hi = mid;
    }
    return lo;
}

__global__ void pool_kernel(const float* __restrict__ hraw,
                            const int* __restrict__ batch,
                            const float* __restrict__ gamma,
                            const float* __restrict__ beta,
                            float* __restrict__ out) {
    int gg = blockIdx.x;
    int c = threadIdx.x;
    const float invn = 1.0f / (float)N_NODES;
    float m = g_bnsum[2 * HID + c] * invn;
    float var = fmaxf(g_bnsq[2 * HID + c] * invn - m * m, 0.f);
    float sc = __ldg(&gamma[c]) * rsqrtf(var + BN_EPS);
    float sh = __ldg(&beta[c]) - m * sc;

    int start = lbound(batch, N_NODES, gg);
    int end = lbound(batch, N_NODES, gg + 1);
    int cnt = end - start;
    float s = 0.f;
    for (int i = start; i < end; i++) {
        float v = fmaf(hraw[i * HID + c], sc, sh);
        s += fmaxf(v, 0.f);
    }
    out[gg * HID + c] = s / fmaxf((float)cnt, 1.f);
}

// ---------------- launch ----------------
extern "C" void kernel_launch(void* const* d_in, const int* in_sizes, int n_in,
                              void* d_out, int out_size) {
    (void)in_sizes; (void)n_in; (void)out_size;
    const float* x       = (const float*)d_in[0];
    const int*   eidx    = (const int*)d_in[1];
    const int*   batch   = (const int*)d_in[2];
    const float* gin_w1  = (const float*)d_in[3];
    const float* gin_b1  = (const float*)d_in[4];
    const float* gin_w2  = (const float*)d_in[5];
    const float* gin_b2  = (const float*)d_in[6];
    const float* sage_wl = (const float*)d_in[7];
    const float* sage_bl = (const float*)d_in[8];
    const float* sage_wr = (const float*)d_in[9];
    const float* bn_g    = (const float*)d_in[10];
    const float* bn_b    = (const float*)d_in[11];
    float* out = (float*)d_out;

    const int* src = eidx;
    const int* dst = eidx + N_EDGES;

    float *p_h0, *p_h1, *p_hbn, *p_ng, *p_t2, *p_bnsum, *p_bnsq;
    cudaGetSymbolAddress((void**)&p_h0, g_h0);
    cudaGetSymbolAddress((void**)&p_h1, g_h1);
    cudaGetSymbolAddress((void**)&p_hbn, g_hbn);
    cudaGetSymbolAddress((void**)&p_ng, g_neigh);
    cudaGetSymbolAddress((void**)&p_t2, g_t2);
    cudaGetSymbolAddress((void**)&p_bnsum, g_bnsum);
    cudaGetSymbolAddress((void**)&p_bnsq, g_bnsq);

    const int M = N_NODES;
    const int ginGrid = (M + 127) / 128;             // 391
    const int sageGrid = (M + 63) / 64;              // 782
    const int aggGrid = (N_NODES * 32 + 255) / 256;
    const int edgeGrid = (N_EDGES + 255) / 256;

    const int fusedSmem = (AS_SIZE + BS_SIZE + TS_SIZE) * 4;  // ~102KB
    static int attr_set = 0;
    if (!attr_set) {
        cudaFuncSetAttribute(gin_mlp_fused_kernel,
                             cudaFuncAttributeMaxDynamicSharedMemorySize, fusedSmem);
        attr_set = 1;
    }

    // CSR build (multi-block scan)
    zero_init_kernel<<<(N_NODES + 255) / 256, 256>>>();
    hist_kernel<<<edgeGrid, 256>>>(dst);
    scan_part1_kernel<<<SCAN_BLOCKS, 256>>>();
    scan_part2_kernel<<<1, 256>>>();
    scan_part3_kernel<<<SCAN_BLOCKS, 256>>>();
    scatter_kernel<<<edgeGrid, 256>>>(src, dst);

    // Layer 0: GIN (fused MLP; stats -> layer 0)
    gin_agg_kernel<<<aggGrid, 256>>>(x);
    gin_mlp_fused_kernel<<<ginGrid, 256, fusedSmem>>>(p_h0, gin_w1, gin_b1, gin_w2, gin_b2,
                                                      p_h1, p_bnsum + 0 * HID, p_bnsq + 0 * HID, M);

    // SAGE layer 0 (uses layer-0 stats inline; stats -> layer 1)
    sage_agg_kernel<<<aggGrid, 256>>>(p_h1, p_hbn, p_ng, bn_g + 0 * HID, bn_b + 0 * HID, 0);
    gemm_sage_kernel<<<sageGrid, 256>>>(p_ng, sage_wl, p_hbn, sage_wr, sage_bl, p_h0,
                                        p_bnsum + 1 * HID, p_bnsq + 1 * HID, M);

    // SAGE layer 1 (uses layer-1 stats; stats -> layer 2)
    sage_agg_kernel<<<aggGrid, 256>>>(p_h0, p_hbn, p_ng, bn_g + 1 * HID, bn_b + 1 * HID, 1);
    gemm_sage_kernel<<<sageGrid, 256>>>(p_ng, sage_wl + HID * HID, p_hbn, sage_wr + HID * HID,
                                        sage_bl + HID, p_t2,
                                        p_bnsum + 2 * HID, p_bnsq + 2 * HID, M);

    // global mean pool (inline BN finalize for layer 2)
    pool_kernel<<<N_GRAPHS, HID>>>(p_t2, batch, bn_g + 2 * HID, bn_b + 2 * HID, out);
}